// round 4
// baseline (speedup 1.0000x reference)
#include <cuda_runtime.h>
#include <utility>

#define BLK 128   // 8 chains x 16 heads

using u64 = unsigned long long;

// ---- packed f32x2 primitives (Blackwell FFMA2 path, PTX-only) ----
__device__ __forceinline__ u64 fma2(u64 a, u64 b, u64 c) {
    u64 d; asm("fma.rn.f32x2 %0, %1, %2, %3;" : "=l"(d) : "l"(a), "l"(b), "l"(c)); return d;
}
__device__ __forceinline__ u64 mul2(u64 a, u64 b) {
    u64 d; asm("mul.rn.f32x2 %0, %1, %2;" : "=l"(d) : "l"(a), "l"(b)); return d;
}
__device__ __forceinline__ u64 add2(u64 a, u64 b) {
    u64 d; asm("add.rn.f32x2 %0, %1, %2;" : "=l"(d) : "l"(a), "l"(b)); return d;
}
__device__ __forceinline__ u64 pack2(float lo, float hi) {
    u64 d; asm("mov.b64 %0, {%1, %2};" : "=l"(d) : "f"(lo), "f"(hi)); return d;
}
__device__ __forceinline__ void unpack2(u64 a, float& lo, float& hi) {
    asm("mov.b64 {%0, %1}, %2;" : "=f"(lo), "=f"(hi) : "l"(a));
}

// ---- compile-time Cl(4,1) Cayley sign: metric (+,+,+,+,-) on bits 0..4 ----
constexpr __host__ __device__ int popc5(int x) {
    int c = 0;
    for (int i = 0; i < 6; i++) c += (x >> i) & 1;
    return c;
}
constexpr __host__ __device__ bool cneg(int a, int b) {
    int s = 0;
    for (int t = a >> 1; t; t >>= 1) s += popc5(t & b);
    bool neg = (s & 1) != 0;
    if ((a & b) & 0x10) neg = !neg;   // e5^2 = -1
    return neg;
}
// within-pair sign flip for row a: sign(a,b^1) = sign(a,b) ^ ra_flip(a)
constexpr __host__ __device__ bool ra_flip(int a) { return (popc5(a >> 1) & 1) != 0; }

constexpr __host__ __device__ bool check_pairs() {
    for (int a = 0; a < 32; a++)
        for (int j = 0; j < 16; j++) {
            bool s0 = cneg(a, a ^ (2 * j));
            bool s1 = cneg(a, a ^ (2 * j + 1));
            if (s1 != (s0 != ra_flip(a))) return false;
        }
    return true;
}
static_assert(check_pairs(), "pair sign lemma violated");

// ---- packed geometric product: Acc pair j gets row-a contribution ----
// lo: acc[2j]   += s(a,a^2j)    * d * psi[a^2j]
// hi: acc[2j+1] += s(a,a^2j+1)  * d * psi[a^2j+1]
// pair index M=(a>>1)^j; even a uses P[M], odd a uses swapped PS[M].
template<int A, int J>
__device__ __forceinline__ void gp_term(u64 V, u64 NV, const u64 (&P)[16], const u64 (&PS)[16], u64 (&Acc)[16]) {
    constexpr int  M   = (A >> 1) ^ J;
    constexpr bool ODD = (A & 1) != 0;
    constexpr bool NEG = cneg(A, A ^ (2 * J));   // sign of lo half
    Acc[J] = fma2(NEG ? NV : V, ODD ? PS[M] : P[M], Acc[J]);
}
template<int A, int... Js>
__device__ __forceinline__ void gp_row(u64 V, u64 NV, const u64 (&P)[16], const u64 (&PS)[16], u64 (&Acc)[16],
                                       std::integer_sequence<int, Js...>) {
    (gp_term<A, Js>(V, NV, P, PS, Acc), ...);
}
template<int A>
__device__ __forceinline__ void gp_a(const u64 (&D)[16], const u64 (&P)[16], const u64 (&PS)[16], u64 (&Acc)[16]) {
    float d0, d1; unpack2(D[A >> 1], d0, d1);
    const float d  = (A & 1) ? d1 : d0;
    const float nd = -d;
    constexpr bool R = ra_flip(A);
    const u64 V  = R ? pack2(d, nd) : pack2(d, d);
    const u64 NV = R ? pack2(nd, d) : pack2(nd, nd);
    gp_row<A>(V, NV, P, PS, Acc, std::make_integer_sequence<int, 16>{});
}
template<int... As>
__device__ __forceinline__ void gp_all(const u64 (&D)[16], const u64 (&P)[16], const u64 (&PS)[16], u64 (&Acc)[16],
                                       std::integer_sequence<int, As...>) {
    (gp_a<As + 1>(D, P, PS, Acc), ...);
}

// shapes: B=16, S=256, N=64, D=6, H=16
// x strides (floats): b: 98304, s: 384, n: 6
__global__ __launch_bounds__(BLK, 1)
void versor_kernel(const float* __restrict__ x,
                   const float* __restrict__ Win,    // [6,512]
                   const float* __restrict__ bin,    // [512]
                   const float* __restrict__ Wout,   // [512,6]
                   const float* __restrict__ bout,   // [6]
                   float* __restrict__ out)
{
    // padded shared: per-head stride 196 floats (784B, 16B aligned; 196 % 32 == 4)
    __shared__ __align__(16) float sWin[16 * 196];   // [h][d][c]
    __shared__ __align__(16) float sWout[16 * 196];  // [h][d][c]
    __shared__ __align__(16) float sBin[16 * 36];    // [h][c]
    __shared__ float sPart[2][16][50];               // [buf][h][ci*6+d]

    const int tid = threadIdx.x;
    const int ci  = tid & 7;        // chain within block
    const int h   = tid >> 3;       // head
    const int b   = blockIdx.x >> 3;
    const int n0  = (blockIdx.x & 7) * 8;

    // ---- stage weights into shared (one-time) ----
    for (int i = tid; i < 3072; i += BLK) {            // Win[d][512]
        int d = i / 512, rem = i - d * 512;
        int hh = rem >> 5, c = rem & 31;
        sWin[hh * 196 + d * 32 + c] = Win[i];
    }
    for (int i = tid; i < 3072; i += BLK) {            // Wout[row][6] -> [h][d][c]
        int row = i / 6, d = i - row * 6;
        int hh = row >> 5, c = row & 31;
        sWout[hh * 196 + d * 32 + c] = Wout[i];
    }
    for (int i = tid; i < 512; i += BLK)
        sBin[(i >> 5) * 36 + (i & 31)] = bin[i];
    __syncthreads();

    const float* xchain = x + (size_t)b * 98304 + (size_t)(n0 + ci) * 6;
    const float* wi = sWin  + h * 196;
    const float* wo = sWout + h * 196;
    const float* bi = sBin  + h * 36;

    // reducer role (threads 0..47): chain rci, component rd
    const int  rci = tid / 6;
    const int  rd  = tid - rci * 6;
    const bool is_red = (tid < 48);
    const float boutr = __ldg(bout + (is_red ? rd : 0));
    const size_t obase = (size_t)b * 98304 + (size_t)(n0 + (is_red ? rci : 0)) * 6 + rd;

    const u64 ONE0 = pack2(1.0f, 0.0f);

    // psi state: 16 packed pairs
    u64 P[16];
#pragma unroll
    for (int j = 0; j < 16; j++) P[j] = 0ull;
    P[0] = ONE0;

    for (int t = 0; t < 256; t++) {
        // ---- load x_t[6] (float2 x3) ----
        const float2* xp2 = (const float2*)(xchain + (size_t)t * 384);
        float2 v0 = __ldg(xp2), v1 = __ldg(xp2 + 1), v2 = __ldg(xp2 + 2);
        const float xv[6] = { v0.x, v0.y, v1.x, v1.y, v2.x, v2.y };

        // ---- embed: U = b_in + x @ W_in (this head's 32 cols, packed) ----
        u64 U[16];
        {
            const ulonglong2* b2 = (const ulonglong2*)bi;
#pragma unroll
            for (int q = 0; q < 8; q++) {
                ulonglong2 bb = b2[q];
                U[q * 2]     = bb.x;
                U[q * 2 + 1] = bb.y;
            }
        }
#pragma unroll
        for (int d = 0; d < 6; d++) {
            const u64 X2 = pack2(xv[d], xv[d]);
            const ulonglong2* w2 = (const ulonglong2*)(wi + d * 32);
#pragma unroll
            for (int q = 0; q < 8; q++) {
                ulonglong2 w = w2[q];
                U[q * 2]     = fma2(X2, w.x, U[q * 2]);
                U[q * 2 + 1] = fma2(X2, w.y, U[q * 2 + 1]);
            }
        }

        // ---- delta_r = normalize(U + e0) ----
        U[0] = add2(U[0], ONE0);
        {
            u64 q0 = mul2(U[0], U[0]), q1 = mul2(U[1], U[1]);
            u64 q2 = mul2(U[2], U[2]), q3 = mul2(U[3], U[3]);
#pragma unroll
            for (int j = 4; j < 16; j += 4) {
                q0 = fma2(U[j],     U[j],     q0);
                q1 = fma2(U[j + 1], U[j + 1], q1);
                q2 = fma2(U[j + 2], U[j + 2], q2);
                q3 = fma2(U[j + 3], U[j + 3], q3);
            }
            u64 qs = add2(add2(q0, q1), add2(q2, q3));
            float sl, sh; unpack2(qs, sl, sh);
            float rn = rsqrtf(sl + sh + 1e-12f);
            const u64 RN = pack2(rn, rn);
#pragma unroll
            for (int j = 0; j < 16; j++) U[j] = mul2(U[j], RN);   // U is now dr (packed)
        }

        // ---- swapped psi copy for odd rows ----
        u64 PS[16];
#pragma unroll
        for (int j = 0; j < 16; j++) {
            float lo, hi; unpack2(P[j], lo, hi);
            PS[j] = pack2(hi, lo);
        }

        // ---- GP: Acc = dr (*) psi ----
        u64 Acc[16];
        {
            float d0, d1; unpack2(U[0], d0, d1);
            const u64 V0 = pack2(d0, d0);      // row a=0: all signs +
#pragma unroll
            for (int j = 0; j < 16; j++) Acc[j] = mul2(V0, P[j]);
        }
        gp_all(U, P, PS, Acc, std::make_integer_sequence<int, 31>{});

        // ---- psi = normalize(Acc) ----
        {
            u64 q0 = mul2(Acc[0], Acc[0]), q1 = mul2(Acc[1], Acc[1]);
            u64 q2 = mul2(Acc[2], Acc[2]), q3 = mul2(Acc[3], Acc[3]);
#pragma unroll
            for (int j = 4; j < 16; j += 4) {
                q0 = fma2(Acc[j],     Acc[j],     q0);
                q1 = fma2(Acc[j + 1], Acc[j + 1], q1);
                q2 = fma2(Acc[j + 2], Acc[j + 2], q2);
                q3 = fma2(Acc[j + 3], Acc[j + 3], q3);
            }
            u64 qs = add2(add2(q0, q1), add2(q2, q3));
            float sl, sh; unpack2(qs, sl, sh);
            float rn = rsqrtf(sl + sh + 1e-12f);
            const u64 RN = pack2(rn, rn);
#pragma unroll
            for (int j = 0; j < 16; j++) P[j] = mul2(Acc[j], RN);
        }

        // ---- projection partial: psi @ W_out[.,6] (packed dot) ----
        float pd[6];
#pragma unroll
        for (int d = 0; d < 6; d++) {
            const ulonglong2* w2 = (const ulonglong2*)(wo + d * 32);
            ulonglong2 wa = w2[0], wb = w2[1], wc = w2[2], wd = w2[3];
            u64 a0 = mul2(P[0], wa.x), a1 = mul2(P[1], wa.y);
            u64 a2 = mul2(P[2], wb.x), a3 = mul2(P[3], wb.y);
            a0 = fma2(P[4], wc.x, a0); a1 = fma2(P[5], wc.y, a1);
            a2 = fma2(P[6], wd.x, a2); a3 = fma2(P[7], wd.y, a3);
            ulonglong2 we = w2[4], wf = w2[5], wg = w2[6], wh = w2[7];
            a0 = fma2(P[8],  we.x, a0); a1 = fma2(P[9],  we.y, a1);
            a2 = fma2(P[10], wf.x, a2); a3 = fma2(P[11], wf.y, a3);
            a0 = fma2(P[12], wg.x, a0); a1 = fma2(P[13], wg.y, a1);
            a2 = fma2(P[14], wh.x, a2); a3 = fma2(P[15], wh.y, a3);
            u64 s = add2(add2(a0, a1), add2(a2, a3));
            float sl, sh; unpack2(s, sl, sh);
            pd[d] = sl + sh;
        }

        // ---- cross-head reduce (double-buffered, one barrier per step) ----
        float* pp = &sPart[t & 1][h][ci * 6];
#pragma unroll
        for (int d = 0; d < 6; d++) pp[d] = pd[d];
        __syncthreads();

        if (is_red) {
            float s = boutr;
#pragma unroll
            for (int hh = 0; hh < 16; hh++)
                s += sPart[t & 1][hh][rci * 6 + rd];
            float xvv = __ldg(x + obase + (size_t)t * 384);
            out[obase + (size_t)t * 384] = xvv + s;
        }
    }
}

extern "C" void kernel_launch(void* const* d_in, const int* in_sizes, int n_in,
                              void* d_out, int out_size)
{
    const float* x    = (const float*)d_in[0];
    const float* Win  = (const float*)d_in[1];
    const float* bin  = (const float*)d_in[2];
    const float* Wout = (const float*)d_in[3];
    const float* bout = (const float*)d_in[4];
    float* out = (float*)d_out;

    versor_kernel<<<128, BLK>>>(x, Win, bin, Wout, bout, out);
}

// round 5
// speedup vs baseline: 1.3497x; 1.3497x over previous
#include <cuda_runtime.h>

#define BLK 128   // 8 chains x 16 heads

// transformed weights: matrix-rep coords.
// coord(r,s,im) = (r*4+s)*2 + im
__device__ float g_Win2[16 * 6 * 32];   // [h][d][coord]
__device__ float g_bin2[16 * 32];       // [h][coord]
__device__ float g_Wout2[16 * 6 * 32];  // [h][d][coord]  (includes 1/4 factor)

// ---------------------------------------------------------------------------
// prep: build blade matrices of Cl(4,1) in M4(C) and fold basis change into
// the weights. Runs every launch (deterministic, trivial cost).
// ---------------------------------------------------------------------------
__global__ void prep_kernel(const float* __restrict__ Win,    // [6,512]
                            const float* __restrict__ bin,    // [512]
                            const float* __restrict__ Wout)   // [512,6]
{
    __shared__ float B[32][32];   // blade -> 32 matrix coords

    if (threadIdx.x == 0) {
        float gre[5][4][4], gim[5][4][4];
        for (int i = 0; i < 5; i++)
            for (int r = 0; r < 4; r++)
                for (int s = 0; s < 4; s++) { gre[i][r][s] = 0.f; gim[i][r][s] = 0.f; }
        // g0 = gamma1 = [[0,s1],[s1,0]]
        gre[0][0][3] = 1; gre[0][1][2] = 1; gre[0][2][1] = 1; gre[0][3][0] = 1;
        // g1 = gamma2 = [[0,s2],[s2,0]]
        gim[1][0][3] = -1; gim[1][1][2] = 1; gim[1][2][1] = -1; gim[1][3][0] = 1;
        // g2 = gamma3 = [[0,s3],[s3,0]]
        gre[2][0][2] = 1; gre[2][1][3] = -1; gre[2][2][0] = 1; gre[2][3][1] = -1;
        // g3 = gamma4 = [[0,iI],[-iI,0]]   (square +1)
        gim[3][0][2] = 1; gim[3][1][3] = 1; gim[3][2][0] = -1; gim[3][3][1] = -1;
        // g4 = e5 = i*g0*g1*g2*g3 = diag(i,i,-i,-i)  (square -1)
        gim[4][0][0] = 1; gim[4][1][1] = 1; gim[4][2][2] = -1; gim[4][3][3] = -1;

        for (int a = 0; a < 32; a++) {
            float mre[4][4], mim[4][4];
            for (int r = 0; r < 4; r++)
                for (int s = 0; s < 4; s++) { mre[r][s] = (r == s) ? 1.f : 0.f; mim[r][s] = 0.f; }
            for (int i = 0; i < 5; i++) {
                if (!((a >> i) & 1)) continue;
                float tre[4][4], tim[4][4];
                for (int r = 0; r < 4; r++)
                    for (int s = 0; s < 4; s++) {
                        float xr = 0.f, xi = 0.f;
                        for (int k = 0; k < 4; k++) {
                            xr += mre[r][k] * gre[i][k][s] - mim[r][k] * gim[i][k][s];
                            xi += mre[r][k] * gim[i][k][s] + mim[r][k] * gre[i][k][s];
                        }
                        tre[r][s] = xr; tim[r][s] = xi;
                    }
                for (int r = 0; r < 4; r++)
                    for (int s = 0; s < 4; s++) { mre[r][s] = tre[r][s]; mim[r][s] = tim[r][s]; }
            }
            for (int r = 0; r < 4; r++)
                for (int s = 0; s < 4; s++) {
                    B[a][(r * 4 + s) * 2]     = mre[r][s];
                    B[a][(r * 4 + s) * 2 + 1] = mim[r][s];
                }
        }
    }
    __syncthreads();

    // Win' : [h][d][coord] = sum_c Win[d][h*32+c] * B[c][coord]
    for (int idx = threadIdx.x; idx < 3072; idx += blockDim.x) {
        int d = idx / 512, rem = idx - d * 512;
        int h = rem >> 5, coord = rem & 31;
        float s = 0.f;
        for (int c = 0; c < 32; c++)
            s += Win[d * 512 + h * 32 + c] * B[c][coord];
        g_Win2[(h * 6 + d) * 32 + coord] = s;
    }
    // bin' : [h][coord]
    for (int idx = threadIdx.x; idx < 512; idx += blockDim.x) {
        int h = idx >> 5, coord = idx & 31;
        float s = 0.f;
        for (int c = 0; c < 32; c++)
            s += bin[h * 32 + c] * B[c][coord];
        g_bin2[idx] = s;
    }
    // Wout' : [h][d][coord] = 0.25 * sum_c B[c][coord] * Wout[h*32+c][d]
    for (int idx = threadIdx.x; idx < 3072; idx += blockDim.x) {
        int h = idx / 192, rem = idx - h * 192;
        int d = rem >> 5, coord = rem & 31;
        float s = 0.f;
        for (int c = 0; c < 32; c++)
            s += B[c][coord] * Wout[(h * 32 + c) * 6 + d];
        g_Wout2[(h * 6 + d) * 32 + coord] = 0.25f * s;
    }
}

// ---------------------------------------------------------------------------
// main scan kernel. thread = (chain, head). psi held as 4x4 complex matrix
// (32 float coords). GP = complex 4x4 matmul (256 FMA vs 1024 direct).
// shapes: B=16, S=256, N=64, D=6, H=16; x strides: b 98304, s 384, n 6
// ---------------------------------------------------------------------------
__global__ __launch_bounds__(BLK, 1)
void versor_kernel(const float* __restrict__ x,
                   const float* __restrict__ bout,   // [6]
                   float* __restrict__ out)
{
    // per-head stride 196 floats (196 % 32 == 4 -> conflict-free broadcast)
    __shared__ __align__(16) float sWin[16 * 196];   // [h][d][coord]
    __shared__ __align__(16) float sWout[16 * 196];  // [h][d][coord]
    __shared__ __align__(16) float sBin[16 * 36];    // [h][coord]
    __shared__ float sPart[2][16][50];               // [buf][h][ci*6+d]

    const int tid = threadIdx.x;
    const int ci  = tid & 7;        // chain within block
    const int h   = tid >> 3;       // head
    const int b   = blockIdx.x >> 3;
    const int n0  = (blockIdx.x & 7) * 8;

    // ---- stage transformed weights into shared ----
    for (int i = tid; i < 3072; i += BLK) {
        int hh = i / 192, rr = i - hh * 192;
        sWin[hh * 196 + rr]  = g_Win2[i];
        sWout[hh * 196 + rr] = g_Wout2[i];
    }
    for (int i = tid; i < 512; i += BLK)
        sBin[(i >> 5) * 36 + (i & 31)] = g_bin2[i];
    __syncthreads();

    const float* xchain = x + (size_t)b * 98304 + (size_t)(n0 + ci) * 6;
    const float* wi = sWin  + h * 196;
    const float* wo = sWout + h * 196;
    const float* bi = sBin  + h * 36;

    // reducer role (threads 0..47): chain rci, component rd
    const int  rci = tid / 6;
    const int  rd  = tid - rci * 6;
    const bool is_red = (tid < 48);
    const float boutr = __ldg(bout + (is_red ? rd : 0));
    const size_t obase = (size_t)b * 98304 + (size_t)(n0 + (is_red ? rci : 0)) * 6 + rd;

    // psi matrix coords; psi0 = identity
    float P[32];
#pragma unroll
    for (int k = 0; k < 32; k++) P[k] = 0.0f;
    P[0] = 1.0f; P[10] = 1.0f; P[20] = 1.0f; P[30] = 1.0f;

    for (int t = 0; t < 256; t++) {
        // ---- load x_t[6] ----
        const float2* xp2 = (const float2*)(xchain + (size_t)t * 384);
        float2 v0 = __ldg(xp2), v1 = __ldg(xp2 + 1), v2 = __ldg(xp2 + 2);
        const float xv[6] = { v0.x, v0.y, v1.x, v1.y, v2.x, v2.y };

        // ---- embed straight into matrix coords: U = bin' + x @ Win' ----
        float u[32];
#pragma unroll
        for (int c4 = 0; c4 < 8; c4++) {
            float4 bb = *(const float4*)(bi + c4 * 4);
            u[c4 * 4 + 0] = bb.x; u[c4 * 4 + 1] = bb.y;
            u[c4 * 4 + 2] = bb.z; u[c4 * 4 + 3] = bb.w;
        }
#pragma unroll
        for (int d = 0; d < 6; d++) {
            float xd = xv[d];
#pragma unroll
            for (int c4 = 0; c4 < 8; c4++) {
                float4 w = *(const float4*)(wi + d * 32 + c4 * 4);
                u[c4 * 4 + 0] = fmaf(xd, w.x, u[c4 * 4 + 0]);
                u[c4 * 4 + 1] = fmaf(xd, w.y, u[c4 * 4 + 1]);
                u[c4 * 4 + 2] = fmaf(xd, w.z, u[c4 * 4 + 2]);
                u[c4 * 4 + 3] = fmaf(xd, w.w, u[c4 * 4 + 3]);
            }
        }

        // ---- +1 on scalar blade == add identity matrix ----
        u[0] += 1.0f; u[10] += 1.0f; u[20] += 1.0f; u[30] += 1.0f;

        // ---- normalize: coeff norm^2 = frob^2 / 4 ----
        {
            float s0 = 0.f, s1 = 0.f, s2 = 0.f, s3 = 0.f;
#pragma unroll
            for (int c = 0; c < 32; c += 4) {
                s0 = fmaf(u[c + 0], u[c + 0], s0);
                s1 = fmaf(u[c + 1], u[c + 1], s1);
                s2 = fmaf(u[c + 2], u[c + 2], s2);
                s3 = fmaf(u[c + 3], u[c + 3], s3);
            }
            float rn = rsqrtf(0.25f * ((s0 + s1) + (s2 + s3)) + 1e-12f);
#pragma unroll
            for (int c = 0; c < 32; c++) u[c] *= rn;
        }

        // ---- GP: psi' = U * P  (4x4 complex matmul, 256 FMA) ----
        float acc[32];
#pragma unroll
        for (int r = 0; r < 4; r++) {
#pragma unroll
            for (int s = 0; s < 4; s++) {
                float cre = 0.f, cim = 0.f;
#pragma unroll
                for (int k = 0; k < 4; k++) {
                    float are = u[(r * 4 + k) * 2], aim = u[(r * 4 + k) * 2 + 1];
                    float bre = P[(k * 4 + s) * 2], bim = P[(k * 4 + s) * 2 + 1];
                    cre = fmaf(are, bre, cre);
                    cre = fmaf(-aim, bim, cre);
                    cim = fmaf(are, bim, cim);
                    cim = fmaf(aim, bre, cim);
                }
                acc[(r * 4 + s) * 2]     = cre;
                acc[(r * 4 + s) * 2 + 1] = cim;
            }
        }

        // ---- normalize psi ----
        {
            float s0 = 0.f, s1 = 0.f, s2 = 0.f, s3 = 0.f;
#pragma unroll
            for (int c = 0; c < 32; c += 4) {
                s0 = fmaf(acc[c + 0], acc[c + 0], s0);
                s1 = fmaf(acc[c + 1], acc[c + 1], s1);
                s2 = fmaf(acc[c + 2], acc[c + 2], s2);
                s3 = fmaf(acc[c + 3], acc[c + 3], s3);
            }
            float rn2 = rsqrtf(0.25f * ((s0 + s1) + (s2 + s3)) + 1e-12f);
#pragma unroll
            for (int c = 0; c < 32; c++) P[c] = acc[c] * rn2;
        }

        // ---- projection partial: P (matrix coords) . Wout'[d] ----
        float pd[6];
#pragma unroll
        for (int d = 0; d < 6; d++) {
            float a0 = 0.f, a1 = 0.f, a2 = 0.f, a3 = 0.f;
#pragma unroll
            for (int c4 = 0; c4 < 8; c4++) {
                float4 w = *(const float4*)(wo + d * 32 + c4 * 4);
                a0 = fmaf(P[c4 * 4 + 0], w.x, a0);
                a1 = fmaf(P[c4 * 4 + 1], w.y, a1);
                a2 = fmaf(P[c4 * 4 + 2], w.z, a2);
                a3 = fmaf(P[c4 * 4 + 3], w.w, a3);
            }
            pd[d] = (a0 + a1) + (a2 + a3);
        }

        // ---- cross-head reduce (double-buffered, one barrier per step) ----
        float* pp = &sPart[t & 1][h][ci * 6];
#pragma unroll
        for (int d = 0; d < 6; d++) pp[d] = pd[d];
        __syncthreads();

        if (is_red) {
            float s = boutr;
#pragma unroll
            for (int hh = 0; hh < 16; hh++)
                s += sPart[t & 1][hh][rci * 6 + rd];
            float xvv = __ldg(x + obase + (size_t)t * 384);
            out[obase + (size_t)t * 384] = xvv + s;
        }
    }
}

extern "C" void kernel_launch(void* const* d_in, const int* in_sizes, int n_in,
                              void* d_out, int out_size)
{
    const float* x    = (const float*)d_in[0];
    const float* Win  = (const float*)d_in[1];
    const float* bin  = (const float*)d_in[2];
    const float* Wout = (const float*)d_in[3];
    const float* bout = (const float*)d_in[4];
    float* out = (float*)d_out;

    prep_kernel<<<1, 256>>>(Win, bin, Wout);
    versor_kernel<<<128, BLK>>>(x, bout, out);
}